// round 10
// baseline (speedup 1.0000x reference)
#include <cuda_runtime.h>
#include <cstdint>

// Single fused persistent kernel: Linear (16x3 GEMV) + 3x channel-weighted
// reductions. Block tiles of 128 float4 outputs, 2-way C split (2KB contiguous
// DRAM streams per channel), full-unroll register load batching, streaming
// cache hints. One __syncthreads per tile: the combine-sync also publishes the
// prefetched next-tile id; part[] is double-buffered by iteration parity so
// cross-iteration reuse is race-free. Self-resetting counters for graph replay.
// Inputs: 0 gap[16,448], 1 out1[16,64,15,64,64], 2 out2[16,128,8,32,32],
//         3 out3[16,256,4,16,16], 4 weight[3,448], 5 bias[3]
// Output: fc[48] | vis1[983040] | vis2[131072] | vis3[16384]  (float)

#define BATCH 16
#define KDIM  448

#define SV1 15360   // spatial float4s per batch image
#define SV2 2048
#define SV3 256

// block tiles: 128 float4 outputs each, 2-way C split across 256 threads.
// tile 0 = fc; then heavy-first (LPT): region3, region2, region1.
#define NT3 32      // 16*256/128
#define NT2 256     // 16*2048/128
#define NT1 1920    // 16*15360/128
#define T3_BEG 1
#define T2_BEG (1 + NT3)
#define T1_BEG (1 + NT3 + NT2)
#define TOTAL_TILES (1 + NT3 + NT2 + NT1)   // 2209

#define OUT_FC 0
#define OUT_V1 48
#define OUT_V2 (48 + 983040)
#define OUT_V3 (48 + 983040 + 131072)

#define GRID_MAIN 592   // 4 blocks/SM * 148 SMs — single resident wave

__device__ int g_ctr  = GRID_MAIN;   // tiles 0..591 are statically assigned
__device__ int g_done = 0;

__device__ __forceinline__ float4 ldcs4(const float4* p) {
    float4 v;
    asm volatile("ld.global.cs.v4.f32 {%0,%1,%2,%3}, [%4];"
                 : "=f"(v.x), "=f"(v.y), "=f"(v.z), "=f"(v.w) : "l"(p));
    return v;
}
__device__ __forceinline__ void stcs4(float4* p, float4 v) {
    asm volatile("st.global.cs.v4.f32 [%0], {%1,%2,%3,%4};"
                 :: "l"(p), "f"(v.x), "f"(v.y), "f"(v.z), "f"(v.w));
}

// One block tile: 128 float4 outputs, threads split C into 2 groups.
// The single __syncthreads inside doubles as the publication point for the
// prefetched next-tile id written by tid 0 before this call.
template<int C, int SV>
__device__ __forceinline__ void do_tile(const float* __restrict__ src,
                                        float* __restrict__ dst,
                                        const float* __restrict__ wsm,
                                        float4* __restrict__ part,  // [128] (parity buffer)
                                        int lt)
{
    constexpr int CC = C / 2;
    int tid = threadIdx.x;
    int o = tid & 127;
    int g = tid >> 7;           // 0..1 channel group
    int v = lt * 128 + o;       // float4 output index within region
    int b = v / SV;
    int sv = v - b * SV;

    const float4* in = reinterpret_cast<const float4*>(src)
                       + b * (C * SV) + sv + (g * CC) * SV;
    const float* wg = wsm + g * CC;

    float4 a0 = make_float4(0.f, 0.f, 0.f, 0.f);
    float4 a1 = make_float4(0.f, 0.f, 0.f, 0.f);
#pragma unroll
    for (int c = 0; c < CC; c += 8) {
        float4 x0 = ldcs4(in + (c + 0) * SV);
        float4 x1 = ldcs4(in + (c + 1) * SV);
        float4 x2 = ldcs4(in + (c + 2) * SV);
        float4 x3 = ldcs4(in + (c + 3) * SV);
        float4 x4 = ldcs4(in + (c + 4) * SV);
        float4 x5 = ldcs4(in + (c + 5) * SV);
        float4 x6 = ldcs4(in + (c + 6) * SV);
        float4 x7 = ldcs4(in + (c + 7) * SV);
        float w0 = wg[c + 0], w1 = wg[c + 1], w2 = wg[c + 2], w3 = wg[c + 3];
        float w4 = wg[c + 4], w5 = wg[c + 5], w6 = wg[c + 6], w7 = wg[c + 7];
        a0.x += w0 * x0.x; a0.y += w0 * x0.y; a0.z += w0 * x0.z; a0.w += w0 * x0.w;
        a1.x += w1 * x1.x; a1.y += w1 * x1.y; a1.z += w1 * x1.z; a1.w += w1 * x1.w;
        a0.x += w2 * x2.x; a0.y += w2 * x2.y; a0.z += w2 * x2.z; a0.w += w2 * x2.w;
        a1.x += w3 * x3.x; a1.y += w3 * x3.y; a1.z += w3 * x3.z; a1.w += w3 * x3.w;
        a0.x += w4 * x4.x; a0.y += w4 * x4.y; a0.z += w4 * x4.z; a0.w += w4 * x4.w;
        a1.x += w5 * x5.x; a1.y += w5 * x5.y; a1.z += w5 * x5.z; a1.w += w5 * x5.w;
        a0.x += w6 * x6.x; a0.y += w6 * x6.y; a0.z += w6 * x6.z; a0.w += w6 * x6.w;
        a1.x += w7 * x7.x; a1.y += w7 * x7.y; a1.z += w7 * x7.z; a1.w += w7 * x7.w;
    }
    float4 acc = make_float4(a0.x + a1.x, a0.y + a1.y, a0.z + a1.z, a0.w + a1.w);

    if (g != 0) part[o] = acc;
    __syncthreads();            // orders: part write, AND tid0's s_tile prefetch
    if (g == 0) {
        float4 p0 = part[o];
        acc.x += p0.x; acc.y += p0.y; acc.z += p0.z; acc.w += p0.w;
        stcs4(reinterpret_cast<float4*>(dst) + v, acc);
    }
}

__global__ void __launch_bounds__(256, 4)
fused_all_kernel(const float* __restrict__ gap,
                 const float* __restrict__ out1,
                 const float* __restrict__ out2,
                 const float* __restrict__ out3,
                 const float* __restrict__ weight,
                 const float* __restrict__ bias,
                 float* __restrict__ dout)
{
    __shared__ float  wsm[KDIM];     // combined 0.5*(w0+w1)
    __shared__ float4 part[2][128];  // parity double-buffer
    __shared__ int    s_tile;

    int tid = threadIdx.x;
    for (int k = tid; k < KDIM; k += 256)
        wsm[k] = 0.5f * (weight[k] + weight[KDIM + k]);
    __syncthreads();                 // wsm visible before first tile

    int t = blockIdx.x;              // static first tile (no startup atomic storm)
    int it = 0;                      // iteration parity for part[] reuse safety
    while (t < TOTAL_TILES) {
        // prefetch NEXT tile id; published by do_tile's internal sync
        if (tid == 0) s_tile = atomicAdd(&g_ctr, 1);
        float4* pb = part[it & 1];

        if (t >= T1_BEG) {
            do_tile<64, SV1>(out1, dout + OUT_V1, wsm, pb, t - T1_BEG);
        } else if (t >= T2_BEG) {
            do_tile<128, SV2>(out2, dout + OUT_V2, wsm + 64, pb, t - T2_BEG);
        } else if (t >= T3_BEG) {
            do_tile<256, SV3>(out3, dout + OUT_V3, wsm + 192, pb, t - T3_BEG);
        } else {
            // fc tile: fc[b][j] = gap[b] . weight[j] + bias[j]  (48 outputs)
            if (tid < BATCH * 3) {
                int b = tid / 3, j = tid % 3;
                const float4* g4 = reinterpret_cast<const float4*>(gap + b * KDIM);
                const float4* w4 = reinterpret_cast<const float4*>(weight + j * KDIM);
                float acc = 0.f;
#pragma unroll 8
                for (int k = 0; k < KDIM / 4; ++k) {
                    float4 a = g4[k], w = w4[k];
                    acc += a.x * w.x + a.y * w.y + a.z * w.z + a.w * w.w;
                }
                dout[OUT_FC + tid] = acc + bias[j];
            }
            __syncthreads();         // fc path has no internal sync: publish s_tile
        }

        t = s_tile;                  // safe: a sync separated the write from this read
        ++it;
    }

    // self-reset: last block out restores counters for the next graph replay.
    if (tid == 0) {
        __threadfence();
        int d = atomicAdd(&g_done, 1);
        if (d == GRID_MAIN - 1) {
            g_ctr  = GRID_MAIN;
            g_done = 0;
            __threadfence();
        }
    }
}

extern "C" void kernel_launch(void* const* d_in, const int* in_sizes, int n_in,
                              void* d_out, int out_size)
{
    const float* gap    = (const float*)d_in[0];
    const float* out1   = (const float*)d_in[1];
    const float* out2   = (const float*)d_in[2];
    const float* out3   = (const float*)d_in[3];
    const float* weight = (const float*)d_in[4];
    const float* bias   = (const float*)d_in[5];
    float* dout = (float*)d_out;

    fused_all_kernel<<<GRID_MAIN, 256>>>(gap, out1, out2, out3, weight, bias, dout);
}

// round 11
// speedup vs baseline: 1.0705x; 1.0705x over previous
#include <cuda_runtime.h>
#include <cstdint>

// Single fused persistent kernel: Linear (16x3 GEMV) + 3x channel-weighted
// reductions. Cost-uniform 32KB tiles (r1: 32 outs x C64, r2: 16 outs x C128,
// r3: 8 outs x C256) -> every tile is 8 strided float4 loads per thread; the
// fine granularity shrinks the end-of-kernel drain tail ~4x. One sync per
// tile (combine sync also publishes prefetched tile id); parity-buffered
// partials; streaming cache hints; self-resetting counters for graph replay.
// Inputs: 0 gap[16,448], 1 out1[16,64,15,64,64], 2 out2[16,128,8,32,32],
//         3 out3[16,256,4,16,16], 4 weight[3,448], 5 bias[3]
// Output: fc[48] | vis1[983040] | vis2[131072] | vis3[16384]  (float)

#define BATCH 16
#define KDIM  448

#define SV1 15360   // spatial float4s per batch image
#define SV2 2048
#define SV3 256

// uniform 32KB tiles
#define NT3 512     // 4096 f4 outs / 8
#define NT2 2048    // 32768 f4 outs / 16
#define NT1 7680    // 245760 f4 outs / 32
#define T3_BEG 1
#define T2_BEG (1 + NT3)
#define T1_BEG (1 + NT3 + NT2)
#define TOTAL_TILES (1 + NT3 + NT2 + NT1)   // 10241

#define OUT_FC 0
#define OUT_V1 48
#define OUT_V2 (48 + 983040)
#define OUT_V3 (48 + 983040 + 131072)

#define GRID_MAIN 592   // 4 blocks/SM * 148 SMs — single resident wave

__device__ int g_ctr  = GRID_MAIN;   // tiles 0..591 statically assigned
__device__ int g_done = 0;

__device__ __forceinline__ float4 ldcs4(const float4* p) {
    float4 v;
    asm volatile("ld.global.cs.v4.f32 {%0,%1,%2,%3}, [%4];"
                 : "=f"(v.x), "=f"(v.y), "=f"(v.z), "=f"(v.w) : "l"(p));
    return v;
}
__device__ __forceinline__ void stcs4(float4* p, float4 v) {
    asm volatile("st.global.cs.v4.f32 [%0], {%1,%2,%3,%4};"
                 :: "l"(p), "f"(v.x), "f"(v.y), "f"(v.z), "f"(v.w));
}

// Uniform tile: OUTS float4 outputs, G = 256/OUTS channel groups, CC = C/G = 8
// strided loads per thread. Internal __syncthreads publishes tid0's s_tile.
template<int C, int OUTS, int SV>
__device__ __forceinline__ void do_tile(const float* __restrict__ src,
                                        float* __restrict__ dst,
                                        const float* __restrict__ wsm,
                                        float4* __restrict__ part,  // [256-OUTS]
                                        int lt)
{
    constexpr int G  = 256 / OUTS;
    constexpr int CC = C / G;          // == 8 for all regions
    static_assert(CC == 8, "uniform tiles expect 8 loads/thread");

    int tid = threadIdx.x;
    int o = tid % OUTS;
    int g = tid / OUTS;
    int v = lt * OUTS + o;             // float4 output index within region
    int b = v / SV;
    int sv = v - b * SV;

    const float4* in = reinterpret_cast<const float4*>(src)
                       + b * (C * SV) + sv + (g * CC) * SV;
    const float* wg = wsm + g * CC;

    float4 x0 = ldcs4(in + 0 * SV);
    float4 x1 = ldcs4(in + 1 * SV);
    float4 x2 = ldcs4(in + 2 * SV);
    float4 x3 = ldcs4(in + 3 * SV);
    float4 x4 = ldcs4(in + 4 * SV);
    float4 x5 = ldcs4(in + 5 * SV);
    float4 x6 = ldcs4(in + 6 * SV);
    float4 x7 = ldcs4(in + 7 * SV);
    float w0 = wg[0], w1 = wg[1], w2 = wg[2], w3 = wg[3];
    float w4 = wg[4], w5 = wg[5], w6 = wg[6], w7 = wg[7];

    float4 a0, a1;
    a0.x = w0 * x0.x; a0.y = w0 * x0.y; a0.z = w0 * x0.z; a0.w = w0 * x0.w;
    a1.x = w1 * x1.x; a1.y = w1 * x1.y; a1.z = w1 * x1.z; a1.w = w1 * x1.w;
    a0.x += w2 * x2.x; a0.y += w2 * x2.y; a0.z += w2 * x2.z; a0.w += w2 * x2.w;
    a1.x += w3 * x3.x; a1.y += w3 * x3.y; a1.z += w3 * x3.z; a1.w += w3 * x3.w;
    a0.x += w4 * x4.x; a0.y += w4 * x4.y; a0.z += w4 * x4.z; a0.w += w4 * x4.w;
    a1.x += w5 * x5.x; a1.y += w5 * x5.y; a1.z += w5 * x5.z; a1.w += w5 * x5.w;
    a0.x += w6 * x6.x; a0.y += w6 * x6.y; a0.z += w6 * x6.z; a0.w += w6 * x6.w;
    a1.x += w7 * x7.x; a1.y += w7 * x7.y; a1.z += w7 * x7.z; a1.w += w7 * x7.w;
    float4 acc = make_float4(a0.x + a1.x, a0.y + a1.y, a0.z + a1.z, a0.w + a1.w);

    if (g != 0) part[(g - 1) * OUTS + o] = acc;
    __syncthreads();            // orders part writes AND tid0's s_tile prefetch
    if (g == 0) {
#pragma unroll
        for (int j = 0; j < G - 1; ++j) {
            float4 p = part[j * OUTS + o];
            acc.x += p.x; acc.y += p.y; acc.z += p.z; acc.w += p.w;
        }
        stcs4(reinterpret_cast<float4*>(dst) + v, acc);
    }
}

__global__ void __launch_bounds__(256, 4)
fused_all_kernel(const float* __restrict__ gap,
                 const float* __restrict__ out1,
                 const float* __restrict__ out2,
                 const float* __restrict__ out3,
                 const float* __restrict__ weight,
                 const float* __restrict__ bias,
                 float* __restrict__ dout)
{
    __shared__ float  wsm[KDIM];     // combined 0.5*(w0+w1)
    __shared__ float4 part[2][248];  // parity double-buffer (max G-1=31 x 8)
    __shared__ int    s_tile;

    int tid = threadIdx.x;
    for (int k = tid; k < KDIM; k += 256)
        wsm[k] = 0.5f * (weight[k] + weight[KDIM + k]);
    __syncthreads();                 // wsm visible before first tile

    int t = blockIdx.x;              // static first tile (no startup storm)
    int it = 0;                      // parity for part[] reuse safety
    while (t < TOTAL_TILES) {
        if (tid == 0) s_tile = atomicAdd(&g_ctr, 1);
        float4* pb = part[it & 1];

        if (t >= T1_BEG) {
            do_tile<64, 32, SV1>(out1, dout + OUT_V1, wsm, pb, t - T1_BEG);
        } else if (t >= T2_BEG) {
            do_tile<128, 16, SV2>(out2, dout + OUT_V2, wsm + 64, pb, t - T2_BEG);
        } else if (t >= T3_BEG) {
            do_tile<256, 8, SV3>(out3, dout + OUT_V3, wsm + 192, pb, t - T3_BEG);
        } else {
            // fc tile: fc[b][j] = gap[b] . weight[j] + bias[j]  (48 outputs)
            if (tid < BATCH * 3) {
                int b = tid / 3, j = tid % 3;
                const float4* g4 = reinterpret_cast<const float4*>(gap + b * KDIM);
                const float4* w4 = reinterpret_cast<const float4*>(weight + j * KDIM);
                float acc = 0.f;
#pragma unroll 8
                for (int k = 0; k < KDIM / 4; ++k) {
                    float4 a = g4[k], w = w4[k];
                    acc += a.x * w.x + a.y * w.y + a.z * w.z + a.w * w.w;
                }
                dout[OUT_FC + tid] = acc + bias[j];
            }
            __syncthreads();         // fc path: publish s_tile
        }

        t = s_tile;                  // a sync separated write from this read
        ++it;
    }

    // self-reset: last block out restores counters for the next graph replay.
    if (tid == 0) {
        __threadfence();
        int d = atomicAdd(&g_done, 1);
        if (d == GRID_MAIN - 1) {
            g_ctr  = GRID_MAIN;
            g_done = 0;
            __threadfence();
        }
    }
}

extern "C" void kernel_launch(void* const* d_in, const int* in_sizes, int n_in,
                              void* d_out, int out_size)
{
    const float* gap    = (const float*)d_in[0];
    const float* out1   = (const float*)d_in[1];
    const float* out2   = (const float*)d_in[2];
    const float* out3   = (const float*)d_in[3];
    const float* weight = (const float*)d_in[4];
    const float* bias   = (const float*)d_in[5];
    float* dout = (float*)d_out;

    fused_all_kernel<<<GRID_MAIN, 256>>>(gap, out1, out2, out3, weight, bias, dout);
}